// round 10
// baseline (speedup 1.0000x reference)
#include <cuda_runtime.h>
#include <cuda_bf16.h>
#include <utility>

// SpeDCT: out[b,:,h,w] = Dinv @ diag(weight[h,w,:]) @ D @ x[b,:,h,w]
// C = 28, H = W = 256, B = 16.
//
// R7: smem-staged I/O. R4/R6 were latency-bound: 28 scalar LDGs per thread
// exposed DRAM latency that 64-reg occupancy couldn't hide, and capping regs
// (R6) just spilled. Now each block stages its 256-pixel x tile through
// shared memory with 7 LDG.128 per thread (front-batched MLP), the compute
// phase reads via ~29-cycle LDS instead of ~800-cycle LDG, and output is
// gathered back through smem into 7 STG.128 streaming stores.
// DCT coefficients remain compile-time float immediates (FFMA-imm, rt=1);
// symmetry folding keeps it at ~784 FMA/pixel.

static constexpr int  Cc   = 28;
static constexpr int  HWp  = 256 * 256;
static constexpr int  TPB  = 256;     // threads/block == pixels/block

// cos(pi * m / 56), exact-to-double via range reduction + Taylor.
__host__ __device__ constexpr double cospi56(int m) {
    int mm = m % 112;
    if (mm < 0) mm += 112;
    if (mm > 56) mm = 112 - mm;
    double x  = 3.141592653589793238462643383279502884 * (double)mm / 56.0;
    double x2 = x * x, t = 1.0, s = 1.0;
    for (int i = 1; i <= 24; ++i) { t *= -x2 / (double)((2 * i - 1) * (2 * i)); s += t; }
    return s;
}

// Forward DCT-II entry: D[k][n] = 2*cos(pi*(2n+1)k/56)
template <int k, int n>
__device__ __forceinline__ float cD() {
    constexpr float v = (float)(2.0 * cospi56((2 * n + 1) * k));
    return v;
}
// Inverse entry: Dinv[n][k] = cos(pi*(2n+1)k/56) * (k==0 ? 0.5 : 1.0) / 28
template <int n, int k>
__device__ __forceinline__ float cDI() {
    constexpr float v = (float)(cospi56((2 * n + 1) * k) * ((k == 0) ? 0.5 : 1.0) / 28.0);
    return v;
}

// Stage 1, n == 0: initialize accumulators with a MUL.
template <int... ks>
__device__ __forceinline__ void s1_init(float (&xd)[Cc], float s, float d,
                                        std::integer_sequence<int, ks...>) {
    ((xd[ks] = ((ks & 1) ? d : s) * cD<ks, 0>()), ...);
}
// Stage 1, n >= 1: accumulate (even k uses s, odd k uses d).
template <int n, int... ks>
__device__ __forceinline__ void s1_acc(float (&xd)[Cc], float s, float d,
                                       std::integer_sequence<int, ks...>) {
    ((xd[ks] = fmaf(((ks & 1) ? d : s), cD<ks, n>(), xd[ks])), ...);
}

template <int... ns>
__device__ __forceinline__ void stage1(float (&xd)[Cc],
                                       const float (&sx)[Cc][TPB], int t,
                                       std::integer_sequence<int, ns...>) {
    (([&] {
         float xa = sx[ns][t];          // conflict-free LDS, lat ~29
         float xb = sx[27 - ns][t];
         if constexpr (ns == 0)
             s1_init(xd, xa + xb, xa - xb, std::make_integer_sequence<int, Cc>{});
         else
             s1_acc<ns>(xd, xa + xb, xa - xb, std::make_integer_sequence<int, Cc>{});
     }()),
     ...);
}

// Stage 2 partial dots: first term MUL, rest FMA.
template <int n, int... js>
__device__ __forceinline__ float dotE(const float (&xd)[Cc],
                                      std::integer_sequence<int, js...>) {
    float e = xd[0] * cDI<n, 0>();
    ((e = fmaf(xd[2 * (js + 1)], cDI<n, 2 * (js + 1)>(), e)), ...);
    return e;
}
template <int n, int... js>
__device__ __forceinline__ float dotO(const float (&xd)[Cc],
                                      std::integer_sequence<int, js...>) {
    float o = xd[1] * cDI<n, 1>();
    ((o = fmaf(xd[2 * (js + 1) + 1], cDI<n, 2 * (js + 1) + 1>(), o)), ...);
    return o;
}

// Stage 2: write results back into this thread's own smem column (no hazard).
template <int... ns>
__device__ __forceinline__ void stage2(const float (&xd)[Cc],
                                       float (&sx)[Cc][TPB], int t,
                                       std::integer_sequence<int, ns...>) {
    (([&] {
         float E = dotE<ns>(xd, std::make_integer_sequence<int, 13>{});
         float O = dotO<ns>(xd, std::make_integer_sequence<int, 13>{});
         sx[ns][t]      = E + O;
         sx[27 - ns][t] = E - O;
     }()),
     ...);
}

__global__ void __launch_bounds__(TPB, 5)   // <=48 regs; peak live ~40 (no LDG buffers now)
spedct_kernel(const float* __restrict__ x, const float* __restrict__ w,
              float* __restrict__ out) {
    __shared__ float sx[Cc][TPB];           // 28 KB tile: [channel][pixel]

    const int t       = threadIdx.x;
    const int b       = blockIdx.x;                 // batch fastest -> weight L2 reuse
    const int hw_base = blockIdx.y * TPB;

    const float* xb = x   + (size_t)b * Cc * HWp + hw_base;
    float*       ob = out + (size_t)b * Cc * HWp + hw_base;

    // ---- Phase 1: bulk load x tile, 7 x LDG.128 per thread (front-batched MLP)
#pragma unroll
    for (int it = 0; it < 7; ++it) {
        int L  = it * TPB + t;      // 0..1791
        int ch = L >> 6;            // 0..27
        int q  = L & 63;            // float4 index within 256 pixels
        float4 v = __ldcs(reinterpret_cast<const float4*>(xb + (size_t)ch * HWp) + q);
        *(reinterpret_cast<float4*>(&sx[ch][0]) + q) = v;   // STS.128, contiguous
    }
    __syncthreads();

    // ---- Phase 2: per-pixel DCT -> filter -> IDCT, smem column-private
    float xd[Cc];
    stage1(xd, sx, t, std::make_integer_sequence<int, 14>{});

    // weight[h,w,:]: 28 contiguous floats per pixel, 112B rows (16B aligned)
    const float4* wv = reinterpret_cast<const float4*>(w + (size_t)(hw_base + t) * Cc);
#pragma unroll
    for (int j = 0; j < 7; ++j) {
        float4 w4 = wv[j];
        xd[4 * j + 0] *= w4.x;
        xd[4 * j + 1] *= w4.y;
        xd[4 * j + 2] *= w4.z;
        xd[4 * j + 3] *= w4.w;
    }

    stage2(xd, sx, t, std::make_integer_sequence<int, 14>{});
    __syncthreads();

    // ---- Phase 3: bulk store, 7 x LDS.128 + STG.128 streaming per thread
#pragma unroll
    for (int it = 0; it < 7; ++it) {
        int L  = it * TPB + t;
        int ch = L >> 6;
        int q  = L & 63;
        float4 v = *(reinterpret_cast<const float4*>(&sx[ch][0]) + q);
        __stcs(reinterpret_cast<float4*>(ob + (size_t)ch * HWp) + q, v);
    }
}

extern "C" void kernel_launch(void* const* d_in, const int* in_sizes, int n_in,
                              void* d_out, int out_size) {
    const float* x = (const float*)d_in[0];   // [16, 28, 256, 256] f32
    const float* w = (const float*)d_in[1];   // [256, 256, 28] f32
    float*     out = (float*)d_out;           // [16, 28, 256, 256] f32

    dim3 grid(16, HWp / TPB);  // (16, 256); batch fastest for weight L2 reuse
    spedct_kernel<<<grid, TPB>>>(x, w, out);
}

// round 12
// speedup vs baseline: 1.2763x; 1.2763x over previous
#include <cuda_runtime.h>
#include <cuda_bf16.h>
#include <utility>

// SpeDCT: out[b,:,h,w] = Dinv @ diag(weight[h,w,:]) @ D @ x[b,:,h,w]
// C = 28, H = W = 256, B = 16.
//
// R11: best structure is R4 (1 px/thread, 64 regs, direct LDG/STG; 46.7us).
// Smem staging (R7) regressed +17us = smem crossbar time is additive on the
// shared L1TEX/MIO unit. Reg caps (R6) spill. So: keep R4 shape, remove
// issue-slot waste instead:
//  - n=0 accumulator init via FFMA-imm into RZ (no zero-init pass)
//  - all folding adds (s,d,E+/-O) as fmaf(b,+/-1.0f,a): imm-form rt=1 vs FADD rt=2
//  - __ldcs / __stcs on the zero-reuse x/out streams; weight (7.3MB, fits L2)
//    keeps default caching and survives across the 16-batch reuse window.
// DCT coefficients remain compile-time float immediates (FFMA-imm, rt=1);
// symmetry folding keeps it at ~784 FMA/pixel.

static constexpr int  Cc  = 28;
static constexpr int  HWp = 256 * 256;

// cos(pi * m / 56), exact-to-double via range reduction + Taylor.
__host__ __device__ constexpr double cospi56(int m) {
    int mm = m % 112;
    if (mm < 0) mm += 112;
    if (mm > 56) mm = 112 - mm;
    double x  = 3.141592653589793238462643383279502884 * (double)mm / 56.0;
    double x2 = x * x, t = 1.0, s = 1.0;
    for (int i = 1; i <= 24; ++i) { t *= -x2 / (double)((2 * i - 1) * (2 * i)); s += t; }
    return s;
}

// Forward DCT-II entry: D[k][n] = 2*cos(pi*(2n+1)k/56)
template <int k, int n>
__device__ __forceinline__ float cD() {
    constexpr float v = (float)(2.0 * cospi56((2 * n + 1) * k));
    return v;
}
// Inverse entry: Dinv[n][k] = cos(pi*(2n+1)k/56) * (k==0 ? 0.5 : 1.0) / 28
template <int n, int k>
__device__ __forceinline__ float cDI() {
    constexpr float v = (float)(cospi56((2 * n + 1) * k) * ((k == 0) ? 0.5 : 1.0) / 28.0);
    return v;
}

// Stage 1, n == 0: initialize accumulators via FFMA-imm with zero addend (RZ).
template <int... ks>
__device__ __forceinline__ void s1_init(float (&xd)[Cc], float s, float d,
                                        std::integer_sequence<int, ks...>) {
    ((xd[ks] = fmaf(((ks & 1) ? d : s), cD<ks, 0>(), 0.0f)), ...);
}
// Stage 1, n >= 1: accumulate (even k uses s, odd k uses d).
template <int n, int... ks>
__device__ __forceinline__ void s1_acc(float (&xd)[Cc], float s, float d,
                                       std::integer_sequence<int, ks...>) {
    ((xd[ks] = fmaf(((ks & 1) ? d : s), cD<ks, n>(), xd[ks])), ...);
}

template <int... ns>
__device__ __forceinline__ void stage1(float (&xd)[Cc], const float* __restrict__ xp,
                                       std::integer_sequence<int, ns...>) {
    (([&] {
         // streaming loads: x has zero reuse; keep L2 for the weight tensor
         float xa = __ldcs(xp + (size_t)ns * HWp);
         float xb = __ldcs(xp + (size_t)(27 - ns) * HWp);
         // fold via FFMA-imm (rt=1) instead of FADD (rt=2)
         float s = fmaf(xb,  1.0f, xa);
         float d = fmaf(xb, -1.0f, xa);
         if constexpr (ns == 0)
             s1_init(xd, s, d, std::make_integer_sequence<int, Cc>{});
         else
             s1_acc<ns>(xd, s, d, std::make_integer_sequence<int, Cc>{});
     }()),
     ...);
}

// Stage 2 partial dots: first term FFMA-imm into RZ, rest FMA-imm.
template <int n, int... js>
__device__ __forceinline__ float dotE(const float (&xd)[Cc],
                                      std::integer_sequence<int, js...>) {
    float e = fmaf(xd[0], cDI<n, 0>(), 0.0f);
    ((e = fmaf(xd[2 * (js + 1)], cDI<n, 2 * (js + 1)>(), e)), ...);
    return e;
}
template <int n, int... js>
__device__ __forceinline__ float dotO(const float (&xd)[Cc],
                                      std::integer_sequence<int, js...>) {
    float o = fmaf(xd[1], cDI<n, 1>(), 0.0f);
    ((o = fmaf(xd[2 * (js + 1) + 1], cDI<n, 2 * (js + 1) + 1>(), o)), ...);
    return o;
}

template <int... ns>
__device__ __forceinline__ void stage2(const float (&xd)[Cc], float* __restrict__ op,
                                       std::integer_sequence<int, ns...>) {
    (([&] {
         float E = dotE<ns>(xd, std::make_integer_sequence<int, 13>{});
         float O = dotO<ns>(xd, std::make_integer_sequence<int, 13>{});
         // combine via FFMA-imm, store streaming (out has zero reuse)
         __stcs(op + (size_t)ns * HWp,        fmaf(O,  1.0f, E));
         __stcs(op + (size_t)(27 - ns) * HWp, fmaf(O, -1.0f, E));
     }()),
     ...);
}

__global__ void __launch_bounds__(256)   // natural regalloc (~64); caps spill (R6)
spedct_kernel(const float* __restrict__ x, const float* __restrict__ w,
              float* __restrict__ out) {
    const int hw = blockIdx.y * blockDim.x + threadIdx.x;  // 0..65535
    const int b  = blockIdx.x;                             // fastest -> weight L2 reuse

    const float* xp = x + (size_t)b * Cc * HWp + hw;
    float*       op = out + (size_t)b * Cc * HWp + hw;

    float xd[Cc];

    // Forward DCT along channels (folded; n=0 initializes via FFMA-imm/RZ)
    stage1(xd, xp, std::make_integer_sequence<int, 14>{});

    // Per-pixel spectral filter. weight rows are 112B each -> 16B aligned.
    // Default caching: the 7.3MB weight tensor fits in L2 and is reused 16x.
    const float4* wv = reinterpret_cast<const float4*>(w + (size_t)hw * Cc);
#pragma unroll
    for (int j = 0; j < 7; ++j) {
        float4 w4 = wv[j];
        xd[4 * j + 0] *= w4.x;
        xd[4 * j + 1] *= w4.y;
        xd[4 * j + 2] *= w4.z;
        xd[4 * j + 3] *= w4.w;
    }

    // Inverse DCT along channels (folded) + streaming stores
    stage2(xd, op, std::make_integer_sequence<int, 14>{});
}

extern "C" void kernel_launch(void* const* d_in, const int* in_sizes, int n_in,
                              void* d_out, int out_size) {
    const float* x = (const float*)d_in[0];   // [16, 28, 256, 256] f32
    const float* w = (const float*)d_in[1];   // [256, 256, 28] f32
    float*     out = (float*)d_out;           // [16, 28, 256, 256] f32

    dim3 grid(16, HWp / 256);  // batch fastest: 16 adjacent blocks share weight slice in L2
    spedct_kernel<<<grid, 256>>>(x, w, out);
}

// round 14
// speedup vs baseline: 1.2771x; 1.0006x over previous
#include <cuda_runtime.h>
#include <cuda_bf16.h>
#include <utility>

// SpeDCT: out[b,:,h,w] = Dinv @ diag(weight[h,w,:]) @ D @ x[b,:,h,w]
// C = 28, H = W = 256, B = 16.
//
// R13: phase-separated register lifetimes for full MLP.
// R12 interleaved loads with accumulation, so with 28 accums live ptxas
// could only keep ~8 of 28 LDGs in flight -> (28/8)*600 = ~2100 cyc exposed
// DRAM latency vs ~840 cyc compute. Now:
//   Phase A: 28 front-batched __ldcs into xv[] (MLP=28, one latency wait)
//   Phase B: fold to s[14]/d[14] (xv dies), k-major stage-1 (peak 56 regs)
//   Phase C: 7 batched LDG.128 weight (s/d dead; L2-resident ~250cyc), mul
//   Phase D: stage-2 dots + paired streaming stores
// DCT coefficients stay compile-time float immediates (FFMA-imm, rt=1);
// symmetry folding keeps ~784 FMA/pixel. All adds are fmaf(x,+/-1,y).

static constexpr int  Cc  = 28;
static constexpr int  HWp = 256 * 256;

// cos(pi * m / 56), exact-to-double via range reduction + Taylor.
__host__ __device__ constexpr double cospi56(int m) {
    int mm = m % 112;
    if (mm < 0) mm += 112;
    if (mm > 56) mm = 112 - mm;
    double x  = 3.141592653589793238462643383279502884 * (double)mm / 56.0;
    double x2 = x * x, t = 1.0, s = 1.0;
    for (int i = 1; i <= 24; ++i) { t *= -x2 / (double)((2 * i - 1) * (2 * i)); s += t; }
    return s;
}

// Forward DCT-II entry: D[k][n] = 2*cos(pi*(2n+1)k/56)
template <int k, int n>
__device__ __forceinline__ float cD() {
    constexpr float v = (float)(2.0 * cospi56((2 * n + 1) * k));
    return v;
}
// Inverse entry: Dinv[n][k] = cos(pi*(2n+1)k/56) * (k==0 ? 0.5 : 1.0) / 28
template <int n, int k>
__device__ __forceinline__ float cDI() {
    constexpr float v = (float)(cospi56((2 * n + 1) * k) * ((k == 0) ? 0.5 : 1.0) / 28.0);
    return v;
}

// ---- Phase A: batched loads ------------------------------------------------
template <int... ns>
__device__ __forceinline__ void load_all(float (&xv)[Cc], const float* __restrict__ xp,
                                         std::integer_sequence<int, ns...>) {
    ((xv[ns] = __ldcs(xp + (size_t)ns * HWp)), ...);
}

// ---- Phase B: fold + k-major stage-1 ---------------------------------------
template <int... ns>
__device__ __forceinline__ void fold_all(const float (&xv)[Cc],
                                         float (&s)[14], float (&d)[14],
                                         std::integer_sequence<int, ns...>) {
    (((s[ns] = fmaf(xv[27 - ns],  1.0f, xv[ns])),
      (d[ns] = fmaf(xv[27 - ns], -1.0f, xv[ns]))), ...);
}

// One spectral bin k: 14-term FFMA-imm dot over s (k even) or d (k odd).
template <int k, int... ns>
__device__ __forceinline__ float s1_dot(const float (&sd)[14],
                                        std::integer_sequence<int, ns...>) {
    float a = fmaf(sd[0], cD<k, 0>(), 0.0f);
    ((a = fmaf(sd[ns + 1], cD<k, ns + 1>(), a)), ...);
    return a;
}

template <int... ks>
__device__ __forceinline__ void stage1(float (&xd)[Cc],
                                       const float (&s)[14], const float (&d)[14],
                                       std::integer_sequence<int, ks...>) {
    ((xd[ks] = ((ks & 1) ? s1_dot<ks>(d, std::make_integer_sequence<int, 13>{})
                         : s1_dot<ks>(s, std::make_integer_sequence<int, 13>{}))), ...);
}

// ---- Phase D: stage-2 partial dots -----------------------------------------
template <int n, int... js>
__device__ __forceinline__ float dotE(const float (&xd)[Cc],
                                      std::integer_sequence<int, js...>) {
    float e = fmaf(xd[0], cDI<n, 0>(), 0.0f);
    ((e = fmaf(xd[2 * (js + 1)], cDI<n, 2 * (js + 1)>(), e)), ...);
    return e;
}
template <int n, int... js>
__device__ __forceinline__ float dotO(const float (&xd)[Cc],
                                      std::integer_sequence<int, js...>) {
    float o = fmaf(xd[1], cDI<n, 1>(), 0.0f);
    ((o = fmaf(xd[2 * (js + 1) + 1], cDI<n, 2 * (js + 1) + 1>(), o)), ...);
    return o;
}

template <int... ns>
__device__ __forceinline__ void stage2(const float (&xd)[Cc], float* __restrict__ op,
                                       std::integer_sequence<int, ns...>) {
    (([&] {
         float E = dotE<ns>(xd, std::make_integer_sequence<int, 13>{});
         float O = dotO<ns>(xd, std::make_integer_sequence<int, 13>{});
         __stcs(op + (size_t)ns * HWp,        fmaf(O,  1.0f, E));
         __stcs(op + (size_t)(27 - ns) * HWp, fmaf(O, -1.0f, E));
     }()),
     ...);
}

__global__ void __launch_bounds__(256)   // natural regalloc; caps spill (R6)
spedct_kernel(const float* __restrict__ x, const float* __restrict__ w,
              float* __restrict__ out) {
    const int hw = blockIdx.y * blockDim.x + threadIdx.x;  // 0..65535
    const int b  = blockIdx.x;                             // fastest -> weight L2 reuse

    const float* xp = x + (size_t)b * Cc * HWp + hw;
    float*       op = out + (size_t)b * Cc * HWp + hw;

    // Phase A: all 28 x loads issued back-to-back (no accumulators live yet)
    float xv[Cc];
    load_all(xv, xp, std::make_integer_sequence<int, Cc>{});

    // Phase B: fold (xv dies), then 28 independent 14-FMA-imm chains
    float s[14], d[14];
    fold_all(xv, s, d, std::make_integer_sequence<int, 14>{});
    float xd[Cc];
    stage1(xd, s, d, std::make_integer_sequence<int, Cc>{});

    // Phase C: batched weight loads (s/d dead; weight is L2-resident, 16x reuse)
    const float4* wv = reinterpret_cast<const float4*>(w + (size_t)hw * Cc);
    float4 w4[7];
#pragma unroll
    for (int j = 0; j < 7; ++j) w4[j] = wv[j];
#pragma unroll
    for (int j = 0; j < 7; ++j) {
        xd[4 * j + 0] *= w4[j].x;
        xd[4 * j + 1] *= w4[j].y;
        xd[4 * j + 2] *= w4[j].z;
        xd[4 * j + 3] *= w4[j].w;
    }

    // Phase D: inverse DCT (folded) + paired streaming stores
    stage2(xd, op, std::make_integer_sequence<int, 14>{});
}

extern "C" void kernel_launch(void* const* d_in, const int* in_sizes, int n_in,
                              void* d_out, int out_size) {
    const float* x = (const float*)d_in[0];   // [16, 28, 256, 256] f32
    const float* w = (const float*)d_in[1];   // [256, 256, 28] f32
    float*     out = (float*)d_out;           // [16, 28, 256, 256] f32

    dim3 grid(16, HWp / 256);  // batch fastest: 16 adjacent blocks share weight slice in L2
    spedct_kernel<<<grid, 256>>>(x, w, out);
}

// round 15
// speedup vs baseline: 1.3164x; 1.0308x over previous
#include <cuda_runtime.h>
#include <cuda_bf16.h>
#include <utility>

// SpeDCT: out[b,:,h,w] = Dinv @ diag(weight[h,w,:]) @ D @ x[b,:,h,w]
// C = 28, H = W = 256, B = 16.
//
// R15: second-level DCT recursion. Even bins of a 28-pt DCT-II are a 14-pt
// DCT-II of the folded sequence -> fold twice: X[4K] from s2=s[m]+s[13-m],
// X[4K+2] from t2=s[m]-s[13-m] (7x7 each); odd bins stay dense (14x14).
// Stage 2 uses the transposed symmetry: E_{13-n} = A_n - B_n with A over
// k%4==0, B over k%4==2. FMA/pixel drops ~868 -> ~700, all FFMA-imm (rt=1).
// Everything else keeps the best-known R13 shell: 1 px/thread, batched
// __ldcs loads, L2-resident weight, __stcs stores, no reg cap.

static constexpr int  Cc  = 28;
static constexpr int  HWp = 256 * 256;

// cos(pi * m / 56), exact-to-double via range reduction + Taylor.
__host__ __device__ constexpr double cospi56(int m) {
    int mm = m % 112;
    if (mm < 0) mm += 112;
    if (mm > 56) mm = 112 - mm;
    double x  = 3.141592653589793238462643383279502884 * (double)mm / 56.0;
    double x2 = x * x, t = 1.0, s = 1.0;
    for (int i = 1; i <= 24; ++i) { t *= -x2 / (double)((2 * i - 1) * (2 * i)); s += t; }
    return s;
}

// Forward DCT-II entry: D[k][n] = 2*cos(pi*(2n+1)k/56)
template <int k, int n>
__device__ __forceinline__ float cD() {
    constexpr float v = (float)(2.0 * cospi56((2 * n + 1) * k));
    return v;
}
// Inverse entry: Dinv[n][k] = cos(pi*(2n+1)k/56) * (k==0 ? 0.5 : 1.0) / 28
template <int n, int k>
__device__ __forceinline__ float cDI() {
    constexpr float v = (float)(cospi56((2 * n + 1) * k) * ((k == 0) ? 0.5 : 1.0) / 28.0);
    return v;
}

// ---- Phase A: batched loads ------------------------------------------------
template <int... ns>
__device__ __forceinline__ void load_all(float (&xv)[Cc], const float* __restrict__ xp,
                                         std::integer_sequence<int, ns...>) {
    ((xv[ns] = __ldcs(xp + (size_t)ns * HWp)), ...);
}

// ---- Stage 1 ----------------------------------------------------------------
// 7-term FFMA-imm dot against cD<K, m>, m = 0..6
template <int K, int... ms>
__device__ __forceinline__ float s1_dot7(const float (&v)[7],
                                         std::integer_sequence<int, ms...>) {
    float a = fmaf(v[0], cD<K, 0>(), 0.0f);
    ((a = fmaf(v[ms + 1], cD<K, ms + 1>(), a)), ...);
    return a;
}
// 14-term FFMA-imm dot against cD<k, n>, n = 0..13
template <int k, int... ns>
__device__ __forceinline__ float s1_dot14(const float (&v)[14],
                                          std::integer_sequence<int, ns...>) {
    float a = fmaf(v[0], cD<k, 0>(), 0.0f);
    ((a = fmaf(v[ns + 1], cD<k, ns + 1>(), a)), ...);
    return a;
}

// Even bins via second-level fold: X[4K] from s2, X[4K+2] from t2 (K=0..6)
template <int... Ks>
__device__ __forceinline__ void s1_even(float (&xd)[Cc], const float (&s2)[7],
                                        const float (&t2)[7],
                                        std::integer_sequence<int, Ks...>) {
    ((xd[4 * Ks]     = s1_dot7<4 * Ks>(s2, std::make_integer_sequence<int, 6>{})), ...);
    ((xd[4 * Ks + 2] = s1_dot7<4 * Ks + 2>(t2, std::make_integer_sequence<int, 6>{})), ...);
}
// Odd bins dense over d (k = 2ks+1, ks = 0..13)
template <int... ks>
__device__ __forceinline__ void s1_odd(float (&xd)[Cc], const float (&d)[14],
                                       std::integer_sequence<int, ks...>) {
    ((xd[2 * ks + 1] = s1_dot14<2 * ks + 1>(d, std::make_integer_sequence<int, 13>{})), ...);
}

// ---- Stage 2 ----------------------------------------------------------------
// A_n: k = 0,4,8,...,24 ; B_n: k = 2,6,...,26 ; O_n: k odd (dense)
template <int n, int... is>
__device__ __forceinline__ float dotA(const float (&y)[Cc],
                                      std::integer_sequence<int, is...>) {
    float a = fmaf(y[0], cDI<n, 0>(), 0.0f);
    ((a = fmaf(y[4 * (is + 1)], cDI<n, 4 * (is + 1)>(), a)), ...);
    return a;
}
template <int n, int... is>
__device__ __forceinline__ float dotB(const float (&y)[Cc],
                                      std::integer_sequence<int, is...>) {
    float a = fmaf(y[2], cDI<n, 2>(), 0.0f);
    ((a = fmaf(y[4 * (is + 1) + 2], cDI<n, 4 * (is + 1) + 2>(), a)), ...);
    return a;
}
template <int n, int... js>
__device__ __forceinline__ float dotO(const float (&y)[Cc],
                                      std::integer_sequence<int, js...>) {
    float o = fmaf(y[1], cDI<n, 1>(), 0.0f);
    ((o = fmaf(y[2 * (js + 1) + 1], cDI<n, 2 * (js + 1) + 1>(), o)), ...);
    return o;
}

// E_n for n=0..13 from folded even-k dots: E[n]=A+B, E[13-n]=A-B (n=0..6)
template <int... ns>
__device__ __forceinline__ void s2_even(float (&E)[14], const float (&y)[Cc],
                                        std::integer_sequence<int, ns...>) {
    (([&] {
         float A = dotA<ns>(y, std::make_integer_sequence<int, 6>{});
         float B = dotB<ns>(y, std::make_integer_sequence<int, 6>{});
         E[ns]      = fmaf(B,  1.0f, A);
         E[13 - ns] = fmaf(B, -1.0f, A);
     }()),
     ...);
}

template <int... ns>
__device__ __forceinline__ void s2_store(const float (&E)[14], const float (&y)[Cc],
                                         float* __restrict__ op,
                                         std::integer_sequence<int, ns...>) {
    (([&] {
         float O = dotO<ns>(y, std::make_integer_sequence<int, 13>{});
         __stcs(op + (size_t)ns * HWp,        fmaf(O,  1.0f, E[ns]));
         __stcs(op + (size_t)(27 - ns) * HWp, fmaf(O, -1.0f, E[ns]));
     }()),
     ...);
}

__global__ void __launch_bounds__(256)   // natural regalloc; caps spill (R6)
spedct_kernel(const float* __restrict__ x, const float* __restrict__ w,
              float* __restrict__ out) {
    const int hw = blockIdx.y * blockDim.x + threadIdx.x;  // 0..65535
    const int b  = blockIdx.x;                             // fastest -> weight L2 reuse

    const float* xp = x + (size_t)b * Cc * HWp + hw;
    float*       op = out + (size_t)b * Cc * HWp + hw;

    // Phase A: all 28 x loads batched
    float xv[Cc];
    load_all(xv, xp, std::make_integer_sequence<int, Cc>{});

    // Fold level 1: s/d (xv dies)
    float s[14], d[14];
#pragma unroll
    for (int n = 0; n < 14; ++n) {
        s[n] = fmaf(xv[27 - n],  1.0f, xv[n]);
        d[n] = fmaf(xv[27 - n], -1.0f, xv[n]);
    }
    // Fold level 2 on the even half: s2/t2 (s dies)
    float s2[7], t2[7];
#pragma unroll
    for (int m = 0; m < 7; ++m) {
        s2[m] = fmaf(s[13 - m],  1.0f, s[m]);
        t2[m] = fmaf(s[13 - m], -1.0f, s[m]);
    }

    // Stage 1: even bins 2x(7x7), odd bins 14x14
    float xd[Cc];
    s1_even(xd, s2, t2, std::make_integer_sequence<int, 7>{});
    s1_odd(xd, d, std::make_integer_sequence<int, 14>{});

    // Spectral filter (weight L2-resident, 16x reuse; 112B rows, 16B aligned)
    const float4* wv = reinterpret_cast<const float4*>(w + (size_t)hw * Cc);
    float4 w4[7];
#pragma unroll
    for (int j = 0; j < 7; ++j) w4[j] = wv[j];
#pragma unroll
    for (int j = 0; j < 7; ++j) {
        xd[4 * j + 0] *= w4[j].x;
        xd[4 * j + 1] *= w4[j].y;
        xd[4 * j + 2] *= w4[j].z;
        xd[4 * j + 3] *= w4[j].w;
    }

    // Stage 2: folded even part (2x(7x7) + combines), dense odd part, stores
    float E[14];
    s2_even(E, xd, std::make_integer_sequence<int, 7>{});
    s2_store(E, xd, op, std::make_integer_sequence<int, 14>{});
}

extern "C" void kernel_launch(void* const* d_in, const int* in_sizes, int n_in,
                              void* d_out, int out_size) {
    const float* x = (const float*)d_in[0];   // [16, 28, 256, 256] f32
    const float* w = (const float*)d_in[1];   // [256, 256, 28] f32
    float*     out = (float*)d_out;           // [16, 28, 256, 256] f32

    dim3 grid(16, HWp / 256);  // batch fastest: 16 adjacent blocks share weight slice in L2
    spedct_kernel<<<grid, 256>>>(x, w, out);
}

// round 16
// speedup vs baseline: 1.4333x; 1.0887x over previous
#include <cuda_runtime.h>
#include <cuda_bf16.h>
#include <utility>

// SpeDCT: out[b,:,h,w] = Dinv @ diag(weight[h,w,:]) @ D @ x[b,:,h,w]
// C = 28, H = W = 256, B = 16.
//
// R16: weight loads through shared memory. R15's per-pixel float4 weight
// loads are L1TEX-pathological: each lane reads its own 112B row, so every
// LDG.128 touches ~28 cache lines -> ~196 of the ~252 L1 wavefronts per
// warp-pixel. Fix: the block's 28KB weight slab is staged with a LINEAR
// coalesced copy (7 LDG.128 = 28 wavefronts + 7 conflict-free STS.128),
// then each thread reads its pixel's 7 float4 via LDS.128 (chunk index
// 7t+j spreads over all 8 16B banks -> minimum crossbar cycles).
// Compute stays R15: double-folded DCT (~700 FFMA-imm/pixel), batched
// __ldcs x loads, __stcs stores, no reg cap.

static constexpr int  Cc  = 28;
static constexpr int  HWp = 256 * 256;
static constexpr int  TPB = 256;

// cos(pi * m / 56), exact-to-double via range reduction + Taylor.
__host__ __device__ constexpr double cospi56(int m) {
    int mm = m % 112;
    if (mm < 0) mm += 112;
    if (mm > 56) mm = 112 - mm;
    double x  = 3.141592653589793238462643383279502884 * (double)mm / 56.0;
    double x2 = x * x, t = 1.0, s = 1.0;
    for (int i = 1; i <= 24; ++i) { t *= -x2 / (double)((2 * i - 1) * (2 * i)); s += t; }
    return s;
}

// Forward DCT-II entry: D[k][n] = 2*cos(pi*(2n+1)k/56)
template <int k, int n>
__device__ __forceinline__ float cD() {
    constexpr float v = (float)(2.0 * cospi56((2 * n + 1) * k));
    return v;
}
// Inverse entry: Dinv[n][k] = cos(pi*(2n+1)k/56) * (k==0 ? 0.5 : 1.0) / 28
template <int n, int k>
__device__ __forceinline__ float cDI() {
    constexpr float v = (float)(cospi56((2 * n + 1) * k) * ((k == 0) ? 0.5 : 1.0) / 28.0);
    return v;
}

// ---- batched x loads ---------------------------------------------------------
template <int... ns>
__device__ __forceinline__ void load_all(float (&xv)[Cc], const float* __restrict__ xp,
                                         std::integer_sequence<int, ns...>) {
    ((xv[ns] = __ldcs(xp + (size_t)ns * HWp)), ...);
}

// ---- Stage 1 -------------------------------------------------------------------
template <int K, int... ms>
__device__ __forceinline__ float s1_dot7(const float (&v)[7],
                                         std::integer_sequence<int, ms...>) {
    float a = fmaf(v[0], cD<K, 0>(), 0.0f);
    ((a = fmaf(v[ms + 1], cD<K, ms + 1>(), a)), ...);
    return a;
}
template <int k, int... ns>
__device__ __forceinline__ float s1_dot14(const float (&v)[14],
                                          std::integer_sequence<int, ns...>) {
    float a = fmaf(v[0], cD<k, 0>(), 0.0f);
    ((a = fmaf(v[ns + 1], cD<k, ns + 1>(), a)), ...);
    return a;
}

template <int... Ks>
__device__ __forceinline__ void s1_even(float (&xd)[Cc], const float (&s2)[7],
                                        const float (&t2)[7],
                                        std::integer_sequence<int, Ks...>) {
    ((xd[4 * Ks]     = s1_dot7<4 * Ks>(s2, std::make_integer_sequence<int, 6>{})), ...);
    ((xd[4 * Ks + 2] = s1_dot7<4 * Ks + 2>(t2, std::make_integer_sequence<int, 6>{})), ...);
}
template <int... ks>
__device__ __forceinline__ void s1_odd(float (&xd)[Cc], const float (&d)[14],
                                       std::integer_sequence<int, ks...>) {
    ((xd[2 * ks + 1] = s1_dot14<2 * ks + 1>(d, std::make_integer_sequence<int, 13>{})), ...);
}

// ---- Stage 2 -------------------------------------------------------------------
template <int n, int... is>
__device__ __forceinline__ float dotA(const float (&y)[Cc],
                                      std::integer_sequence<int, is...>) {
    float a = fmaf(y[0], cDI<n, 0>(), 0.0f);
    ((a = fmaf(y[4 * (is + 1)], cDI<n, 4 * (is + 1)>(), a)), ...);
    return a;
}
template <int n, int... is>
__device__ __forceinline__ float dotB(const float (&y)[Cc],
                                      std::integer_sequence<int, is...>) {
    float a = fmaf(y[2], cDI<n, 2>(), 0.0f);
    ((a = fmaf(y[4 * (is + 1) + 2], cDI<n, 4 * (is + 1) + 2>(), a)), ...);
    return a;
}
template <int n, int... js>
__device__ __forceinline__ float dotO(const float (&y)[Cc],
                                      std::integer_sequence<int, js...>) {
    float o = fmaf(y[1], cDI<n, 1>(), 0.0f);
    ((o = fmaf(y[2 * (js + 1) + 1], cDI<n, 2 * (js + 1) + 1>(), o)), ...);
    return o;
}

template <int... ns>
__device__ __forceinline__ void s2_even(float (&E)[14], const float (&y)[Cc],
                                        std::integer_sequence<int, ns...>) {
    (([&] {
         float A = dotA<ns>(y, std::make_integer_sequence<int, 6>{});
         float B = dotB<ns>(y, std::make_integer_sequence<int, 6>{});
         E[ns]      = fmaf(B,  1.0f, A);
         E[13 - ns] = fmaf(B, -1.0f, A);
     }()),
     ...);
}

template <int... ns>
__device__ __forceinline__ void s2_store(const float (&E)[14], const float (&y)[Cc],
                                         float* __restrict__ op,
                                         std::integer_sequence<int, ns...>) {
    (([&] {
         float O = dotO<ns>(y, std::make_integer_sequence<int, 13>{});
         __stcs(op + (size_t)ns * HWp,        fmaf(O,  1.0f, E[ns]));
         __stcs(op + (size_t)(27 - ns) * HWp, fmaf(O, -1.0f, E[ns]));
     }()),
     ...);
}

__global__ void __launch_bounds__(TPB)   // natural regalloc; caps spill (R6)
spedct_kernel(const float* __restrict__ x, const float* __restrict__ w,
              float* __restrict__ out) {
    // Block's weight slab, linear float4 layout: sw[p*7 + j] = weight[hw_base+p][4j..4j+3]
    __shared__ float4 sw[TPB * 7];      // 28 KB

    const int t       = threadIdx.x;
    const int b       = blockIdx.x;                 // fastest -> weight L2 reuse
    const int hw_base = blockIdx.y * TPB;
    const int hw      = hw_base + t;

    const float* xp = x + (size_t)b * Cc * HWp + hw;
    float*       op = out + (size_t)b * Cc * HWp + hw;

    // ---- Stage the weight slab: straight coalesced copy (global f4 index
    // f == pixel f/7, chunk f%7 already). 7 LDG.128 (4 wavefronts each)
    // + 7 conflict-free STS.128 replace 196 L1 wavefronts of row-gather.
    {
        const float4* wg = reinterpret_cast<const float4*>(w + (size_t)hw_base * Cc);
#pragma unroll
        for (int it = 0; it < 7; ++it)
            sw[it * TPB + t] = __ldg(wg + it * TPB + t);
    }

    // ---- x loads batched (DRAM latency runs concurrently with the barrier)
    float xv[Cc];
    load_all(xv, xp, std::make_integer_sequence<int, Cc>{});

    __syncthreads();

    // ---- Fold level 1 (xv dies), level 2 on even half (s dies)
    float s[14], d[14];
#pragma unroll
    for (int n = 0; n < 14; ++n) {
        s[n] = fmaf(xv[27 - n],  1.0f, xv[n]);
        d[n] = fmaf(xv[27 - n], -1.0f, xv[n]);
    }
    float s2[7], t2[7];
#pragma unroll
    for (int m = 0; m < 7; ++m) {
        s2[m] = fmaf(s[13 - m],  1.0f, s[m]);
        t2[m] = fmaf(s[13 - m], -1.0f, s[m]);
    }

    // ---- Stage 1: even bins 2x(7x7), odd bins 14x14 (all FFMA-imm)
    float xd[Cc];
    s1_even(xd, s2, t2, std::make_integer_sequence<int, 7>{});
    s1_odd(xd, d, std::make_integer_sequence<int, 14>{});

    // ---- Spectral filter from smem: 7 LDS.128, chunk index 7t+j -> all
    // 16B-banks covered uniformly -> minimum crossbar cycles.
#pragma unroll
    for (int j = 0; j < 7; ++j) {
        float4 w4 = sw[t * 7 + j];
        xd[4 * j + 0] *= w4.x;
        xd[4 * j + 1] *= w4.y;
        xd[4 * j + 2] *= w4.z;
        xd[4 * j + 3] *= w4.w;
    }

    // ---- Stage 2: folded even part + dense odd part, paired streaming stores
    float E[14];
    s2_even(E, xd, std::make_integer_sequence<int, 7>{});
    s2_store(E, xd, op, std::make_integer_sequence<int, 14>{});
}

extern "C" void kernel_launch(void* const* d_in, const int* in_sizes, int n_in,
                              void* d_out, int out_size) {
    const float* x = (const float*)d_in[0];   // [16, 28, 256, 256] f32
    const float* w = (const float*)d_in[1];   // [256, 256, 28] f32
    float*     out = (float*)d_out;           // [16, 28, 256, 256] f32

    dim3 grid(16, HWp / TPB);  // batch fastest: 16 adjacent blocks share weight slice in L2
    spedct_kernel<<<grid, TPB>>>(x, w, out);
}

// round 17
// speedup vs baseline: 1.4403x; 1.0049x over previous
#include <cuda_runtime.h>
#include <cuda_bf16.h>
#include <utility>

// SpeDCT: out[b,:,h,w] = Dinv @ diag(weight[h,w,:]) @ D @ x[b,:,h,w]
// C = 28, H = W = 256, B = 16.
//
// R17: per-warp weight staging. R16 (weight transpose via smem) validated
// the L1TEX-wavefront model (44.7 -> 40.3us) but kept a block-wide
// __syncthreads that runs all 8 warps in lockstep against the slowest
// weight LDG. Observation: warp w's 32 pixels own exactly float4 indices
// [224w, 224w+224) of the block slab -> the transpose is warp-local.
// So each warp stages its own 3.5KB slice (7 LDG.128 + 7 STS.128) and only
// __syncwarp()s, placed after fold+stage1 so the STS->LDS chain hides under
// ~500 cyc of FFMA-imm work. Warps are fully independent.
// Compute stays R15/R16: double-folded DCT (~700 FFMA-imm/pixel), batched
// __ldcs x loads, __stcs stores, no reg cap.

static constexpr int  Cc  = 28;
static constexpr int  HWp = 256 * 256;
static constexpr int  TPB = 256;

// cos(pi * m / 56), exact-to-double via range reduction + Taylor.
__host__ __device__ constexpr double cospi56(int m) {
    int mm = m % 112;
    if (mm < 0) mm += 112;
    if (mm > 56) mm = 112 - mm;
    double x  = 3.141592653589793238462643383279502884 * (double)mm / 56.0;
    double x2 = x * x, t = 1.0, s = 1.0;
    for (int i = 1; i <= 24; ++i) { t *= -x2 / (double)((2 * i - 1) * (2 * i)); s += t; }
    return s;
}

// Forward DCT-II entry: D[k][n] = 2*cos(pi*(2n+1)k/56)
template <int k, int n>
__device__ __forceinline__ float cD() {
    constexpr float v = (float)(2.0 * cospi56((2 * n + 1) * k));
    return v;
}
// Inverse entry: Dinv[n][k] = cos(pi*(2n+1)k/56) * (k==0 ? 0.5 : 1.0) / 28
template <int n, int k>
__device__ __forceinline__ float cDI() {
    constexpr float v = (float)(cospi56((2 * n + 1) * k) * ((k == 0) ? 0.5 : 1.0) / 28.0);
    return v;
}

// ---- batched x loads ---------------------------------------------------------
template <int... ns>
__device__ __forceinline__ void load_all(float (&xv)[Cc], const float* __restrict__ xp,
                                         std::integer_sequence<int, ns...>) {
    ((xv[ns] = __ldcs(xp + (size_t)ns * HWp)), ...);
}

// ---- Stage 1 -------------------------------------------------------------------
template <int K, int... ms>
__device__ __forceinline__ float s1_dot7(const float (&v)[7],
                                         std::integer_sequence<int, ms...>) {
    float a = fmaf(v[0], cD<K, 0>(), 0.0f);
    ((a = fmaf(v[ms + 1], cD<K, ms + 1>(), a)), ...);
    return a;
}
template <int k, int... ns>
__device__ __forceinline__ float s1_dot14(const float (&v)[14],
                                          std::integer_sequence<int, ns...>) {
    float a = fmaf(v[0], cD<k, 0>(), 0.0f);
    ((a = fmaf(v[ns + 1], cD<k, ns + 1>(), a)), ...);
    return a;
}

template <int... Ks>
__device__ __forceinline__ void s1_even(float (&xd)[Cc], const float (&s2)[7],
                                        const float (&t2)[7],
                                        std::integer_sequence<int, Ks...>) {
    ((xd[4 * Ks]     = s1_dot7<4 * Ks>(s2, std::make_integer_sequence<int, 6>{})), ...);
    ((xd[4 * Ks + 2] = s1_dot7<4 * Ks + 2>(t2, std::make_integer_sequence<int, 6>{})), ...);
}
template <int... ks>
__device__ __forceinline__ void s1_odd(float (&xd)[Cc], const float (&d)[14],
                                       std::integer_sequence<int, ks...>) {
    ((xd[2 * ks + 1] = s1_dot14<2 * ks + 1>(d, std::make_integer_sequence<int, 13>{})), ...);
}

// ---- Stage 2 -------------------------------------------------------------------
template <int n, int... is>
__device__ __forceinline__ float dotA(const float (&y)[Cc],
                                      std::integer_sequence<int, is...>) {
    float a = fmaf(y[0], cDI<n, 0>(), 0.0f);
    ((a = fmaf(y[4 * (is + 1)], cDI<n, 4 * (is + 1)>(), a)), ...);
    return a;
}
template <int n, int... is>
__device__ __forceinline__ float dotB(const float (&y)[Cc],
                                      std::integer_sequence<int, is...>) {
    float a = fmaf(y[2], cDI<n, 2>(), 0.0f);
    ((a = fmaf(y[4 * (is + 1) + 2], cDI<n, 4 * (is + 1) + 2>(), a)), ...);
    return a;
}
template <int n, int... js>
__device__ __forceinline__ float dotO(const float (&y)[Cc],
                                      std::integer_sequence<int, js...>) {
    float o = fmaf(y[1], cDI<n, 1>(), 0.0f);
    ((o = fmaf(y[2 * (js + 1) + 1], cDI<n, 2 * (js + 1) + 1>(), o)), ...);
    return o;
}

template <int... ns>
__device__ __forceinline__ void s2_even(float (&E)[14], const float (&y)[Cc],
                                        std::integer_sequence<int, ns...>) {
    (([&] {
         float A = dotA<ns>(y, std::make_integer_sequence<int, 6>{});
         float B = dotB<ns>(y, std::make_integer_sequence<int, 6>{});
         E[ns]      = fmaf(B,  1.0f, A);
         E[13 - ns] = fmaf(B, -1.0f, A);
     }()),
     ...);
}

template <int... ns>
__device__ __forceinline__ void s2_store(const float (&E)[14], const float (&y)[Cc],
                                         float* __restrict__ op,
                                         std::integer_sequence<int, ns...>) {
    (([&] {
         float O = dotO<ns>(y, std::make_integer_sequence<int, 13>{});
         __stcs(op + (size_t)ns * HWp,        fmaf(O,  1.0f, E[ns]));
         __stcs(op + (size_t)(27 - ns) * HWp, fmaf(O, -1.0f, E[ns]));
     }()),
     ...);
}

__global__ void __launch_bounds__(TPB)   // natural regalloc; caps spill (R6)
spedct_kernel(const float* __restrict__ x, const float* __restrict__ w,
              float* __restrict__ out) {
    // Block weight slab, linear float4 layout: sw[p*7 + j] = weight[hw_base+p][4j..4j+3]
    // Warp w touches only sw[224w .. 224w+224) — staging is warp-private.
    __shared__ float4 sw[TPB * 7];      // 28 KB

    const int t       = threadIdx.x;
    const int lane    = t & 31;
    const int wbase   = (t >> 5) * 224;             // warp's float4 slice base
    const int b       = blockIdx.x;                 // fastest -> weight L2 reuse
    const int hw_base = blockIdx.y * TPB;
    const int hw      = hw_base + t;

    const float* xp = x + (size_t)b * Cc * HWp + hw;
    float*       op = out + (size_t)b * Cc * HWp + hw;

    // ---- Warp-private weight staging: 7 coalesced LDG.128 + 7 STS.128.
    {
        const float4* wg = reinterpret_cast<const float4*>(w + (size_t)hw_base * Cc);
#pragma unroll
        for (int it = 0; it < 7; ++it) {
            int f = wbase + it * 32 + lane;
            sw[f] = __ldg(wg + f);
        }
    }

    // ---- x loads batched (DRAM latency overlaps the weight STS chain)
    float xv[Cc];
    load_all(xv, xp, std::make_integer_sequence<int, Cc>{});

    // ---- Fold level 1 (xv dies), level 2 on even half (s dies)
    float s[14], d[14];
#pragma unroll
    for (int n = 0; n < 14; ++n) {
        s[n] = fmaf(xv[27 - n],  1.0f, xv[n]);
        d[n] = fmaf(xv[27 - n], -1.0f, xv[n]);
    }
    float s2[7], t2[7];
#pragma unroll
    for (int m = 0; m < 7; ++m) {
        s2[m] = fmaf(s[13 - m],  1.0f, s[m]);
        t2[m] = fmaf(s[13 - m], -1.0f, s[m]);
    }

    // ---- Stage 1: even bins 2x(7x7), odd bins 14x14 (all FFMA-imm)
    float xd[Cc];
    s1_even(xd, s2, t2, std::make_integer_sequence<int, 7>{});
    s1_odd(xd, d, std::make_integer_sequence<int, 14>{});

    // ---- Warp-local sync only: my LDS reads only my warp's STS data.
    __syncwarp();

    // ---- Spectral filter from smem: 7 LDS.128, stride-7 f4 index covers
    // all 16B banks uniformly (7 coprime 8) -> minimal crossbar cycles.
#pragma unroll
    for (int j = 0; j < 7; ++j) {
        float4 w4 = sw[t * 7 + j];      // t*7 == wbase + lane*7
        xd[4 * j + 0] *= w4.x;
        xd[4 * j + 1] *= w4.y;
        xd[4 * j + 2] *= w4.z;
        xd[4 * j + 3] *= w4.w;
    }

    // ---- Stage 2: folded even part + dense odd part, paired streaming stores
    float E[14];
    s2_even(E, xd, std::make_integer_sequence<int, 7>{});
    s2_store(E, xd, op, std::make_integer_sequence<int, 14>{});
}

extern "C" void kernel_launch(void* const* d_in, const int* in_sizes, int n_in,
                              void* d_out, int out_size) {
    const float* x = (const float*)d_in[0];   // [16, 28, 256, 256] f32
    const float* w = (const float*)d_in[1];   // [256, 256, 28] f32
    float*     out = (float*)d_out;           // [16, 28, 256, 256] f32

    dim3 grid(16, HWp / TPB);  // batch fastest: 16 adjacent blocks share weight slice in L2
    spedct_kernel<<<grid, TPB>>>(x, w, out);
}